// round 9
// baseline (speedup 1.0000x reference)
#include <cuda_runtime.h>
#include <cstdint>

// EfficientByteMUL — TMA bulk-pipeline version.
// Layout: MARK_AX=0, OP_MUL=1, ALU_LO=16, ALU_HI=32, AX_CARRY_LO=48, AX_CARRY_HI=64,
// OUTPUT_LO=80, OUTPUT_HI=96, BD_DIM=128. GE pos-0 input is 3-sparse:
//   h_j = relu(a*W1[0,j] + b*W1[1,j] + W1[29,j] + b1[j]),  y = sum_j h_j*W2[j,40] + b2[40]
//
// Per block: TMA bulk G->S of 64 tokens (32KB); build coeff table in smem while the
// load is in flight; patch active tokens in smem; TMA bulk S->G of the chunk.

#define TOK_PER_BLOCK 64
#define CHUNK_BYTES   (TOK_PER_BLOCK * 128 * 4)   // 32768

__global__ void __launch_bounds__(256)
byte_mul_tma_kernel(const float* __restrict__ x,
                    float* __restrict__ out,
                    const float* __restrict__ W1,
                    const float* __restrict__ b1,
                    const float* __restrict__ W2,
                    const float* __restrict__ b2,
                    int n_tokens)
{
    __shared__ __align__(128) float  s_data[TOK_PER_BLOCK * 128]; // 32 KB
    __shared__ __align__(16)  float4 s_coeff[256];                // 4 KB
    __shared__ float s_b2;
    __shared__ __align__(8) uint64_t s_mbar;

    const unsigned FULL = 0xffffffffu;
    int tid  = threadIdx.x;
    int warp = tid >> 5;
    int lane = tid & 31;

    int tok0 = blockIdx.x * TOK_PER_BLOCK;
    if (tok0 >= n_tokens) return;
    int ct = n_tokens - tok0; if (ct > TOK_PER_BLOCK) ct = TOK_PER_BLOCK;
    unsigned bytes = (unsigned)ct * 512u;

    // shared addresses (shared-state-space 32-bit)
    uint32_t s_data_addr, s_mbar_addr;
    {
        uint64_t t;
        asm("cvta.to.shared.u64 %0, %1;" : "=l"(t) : "l"((void*)s_data));
        s_data_addr = (uint32_t)t;
        asm("cvta.to.shared.u64 %0, %1;" : "=l"(t) : "l"((void*)&s_mbar));
        s_mbar_addr = (uint32_t)t;
    }

    const char* src = (const char*)(x + (size_t)tok0 * 128);
    char*       dst = (char*)(out + (size_t)tok0 * 128);

    // ---- issue TMA load (tid 0) ----
    if (tid == 0) {
        asm volatile("mbarrier.init.shared.b64 [%0], %1;"
                     :: "r"(s_mbar_addr), "r"(1) : "memory");
        asm volatile("mbarrier.arrive.expect_tx.shared.b64 _, [%0], %1;"
                     :: "r"(s_mbar_addr), "r"(bytes) : "memory");
        asm volatile("cp.async.bulk.shared::cta.global.mbarrier::complete_tx::bytes "
                     "[%0], [%1], %2, [%3];"
                     :: "r"(s_data_addr), "l"(src), "r"(bytes), "r"(s_mbar_addr)
                     : "memory");
    }

    // ---- build coefficient table in smem (overlaps the TMA load) ----
    {
        int j = tid;  // 256 threads
        s_coeff[j] = make_float4(W1[j],
                                 W1[256 + j],
                                 W1[29 * 256 + j] + b1[j],
                                 W2[j * 64 + 40]);
        if (j == 0) s_b2 = b2[40];
    }
    __syncthreads();   // coeffs visible to all; mbarrier init visible before waits

    // ---- wait for TMA data ----
    {
        uint32_t done;
        asm volatile(
            "{\n\t"
            ".reg .pred p;\n\t"
            "mbarrier.try_wait.parity.acquire.cta.shared::cta.b64 p, [%1], %2;\n\t"
            "selp.b32 %0, 1, 0, p;\n\t"
            "}"
            : "=r"(done) : "r"(s_mbar_addr), "r"(0) : "memory");
        if (!done) {
            asm volatile(
                "{\n\t"
                ".reg .pred P1;\n\t"
                "WL_%=:\n\t"
                "mbarrier.try_wait.parity.acquire.cta.shared::cta.b64 P1, [%0], %1, 0x989680;\n\t"
                "@P1 bra.uni WD_%=;\n\t"
                "bra.uni WL_%=;\n\t"
                "WD_%=:\n\t"
                "}"
                :: "r"(s_mbar_addr), "r"(0) : "memory");
        }
    }

    // ---- per-warp: find + process active tokens (8 tokens per warp) ----
    {
        int tbase = warp * 8;                 // this warp's first token in chunk
        bool pred = false;
        if (lane < 8) {
            int t = tbase + lane;
            if (t < ct) {
                float2 m = *reinterpret_cast<const float2*>(&s_data[t * 128]);
                pred = (m.x >= 0.5f) && (m.y >= 0.5f);
            }
        }
        unsigned act = __ballot_sync(FULL, pred);   // bits 0..7

        while (act) {
            int b = __ffs(act) - 1;
            act &= act - 1;
            float* stok = &s_data[(tbase + b) * 128];

            // argmax over four 16-elem segments: [16,32)->lanes4..7, [32,48)->8..11,
            // [48,64)->12..15, [64,80)->16..19 (first-max wins)
            float4 w = make_float4(0.f, 0.f, 0.f, 0.f);
            if (lane >= 4 && lane < 20)
                w = reinterpret_cast<const float4*>(stok)[lane];

            float best = w.x; int bidx = 0;
            if (w.y > best) { best = w.y; bidx = 1; }
            if (w.z > best) { best = w.z; bidx = 2; }
            if (w.w > best) { best = w.w; bidx = 3; }
            int gidx = ((lane & 3) << 2) | bidx;

            #pragma unroll
            for (int off = 1; off <= 2; off <<= 1) {
                float ob = __shfl_xor_sync(FULL, best, off);
                int   oi = __shfl_xor_sync(FULL, gidx, off);
                if (ob > best || (ob == best && oi < gidx)) { best = ob; gidx = oi; }
            }

            int a_lo = __shfl_sync(FULL, gidx, 4);
            int a_hi = __shfl_sync(FULL, gidx, 8);
            int b_lo = __shfl_sync(FULL, gidx, 12);
            int b_hi = __shfl_sync(FULL, gidx, 16);

            float fa = (float)(a_lo | (a_hi << 4));
            float fb = (float)(b_lo | (b_hi << 4));

            // MLP: j = lane + 32*i, coeffs in smem (conflict-free LDS.128)
            float acc = 0.0f;
            #pragma unroll
            for (int i = 0; i < 8; i++) {
                float4 c = s_coeff[lane + 32 * i];
                float h = fmaf(fa, c.x, fmaf(fb, c.y, c.z));
                h = fmaxf(h, 0.0f);
                acc = fmaf(h, c.w, acc);
            }
            #pragma unroll
            for (int off = 16; off; off >>= 1)
                acc += __shfl_xor_sync(FULL, acc, off);
            acc += s_b2;

            int res = ((int)rintf(acc)) & 255;   // round-half-even == jnp.round
            if (lane == 0) {
                stok[80 + (res & 15)] += 2.0f;
                stok[96 + (res >> 4)] += 2.0f;
            }
        }
    }

    __syncthreads();

    // ---- TMA store S->G, then drain ----
    if (tid == 0) {
        asm volatile("fence.proxy.async.shared::cta;" ::: "memory");
        asm volatile("cp.async.bulk.global.shared::cta.bulk_group [%0], [%1], %2;"
                     :: "l"(dst), "r"(s_data_addr), "r"(bytes) : "memory");
        asm volatile("cp.async.bulk.commit_group;" ::: "memory");
        asm volatile("cp.async.bulk.wait_group 0;" ::: "memory");
    }
}

extern "C" void kernel_launch(void* const* d_in, const int* in_sizes, int n_in,
                              void* d_out, int out_size)
{
    const float* x  = (const float*)d_in[0];  // [8, 8192, 128]
    const float* W1 = (const float*)d_in[1];  // [64, 256]
    const float* b1 = (const float*)d_in[2];  // [256]
    const float* W2 = (const float*)d_in[3];  // [256, 64]
    const float* b2 = (const float*)d_in[4];  // [64]
    float* out = (float*)d_out;

    int n_tokens = in_sizes[0] / 128;         // 65536
    int blocks = (n_tokens + TOK_PER_BLOCK - 1) / TOK_PER_BLOCK;  // 1024

    byte_mul_tma_kernel<<<blocks, 256>>>(x, out, W1, b1, W2, b2, n_tokens);
}

// round 11
// speedup vs baseline: 1.1382x; 1.1382x over previous
#include <cuda_runtime.h>
#include <cstdint>

// EfficientByteMUL — double-buffered TMA bulk pipeline.
// Layout: MARK_AX=0, OP_MUL=1, ALU_LO=16, ALU_HI=32, AX_CARRY_LO=48, AX_CARRY_HI=64,
// OUTPUT_LO=80, OUTPUT_HI=96, BD_DIM=128. GE pos-0 input is 3-sparse:
//   h_j = relu(a*W1[0,j] + b*W1[1,j] + W1[29,j] + b1[j]),  y = sum_j h_j*W2[j,40] + b2[40]
//
// Each CTA owns ~4-5 chunks of 32 tokens (16 KB). Pipeline per iteration:
//   [tid0] wait_group.read (slot free) ; issue TMA load of NEXT chunk
//   [all ] mbarrier-wait current chunk ; patch active tokens in smem
//   [tid0] fence.proxy.async ; bulk store ; commit
// So chunk i+1's G->S latency is hidden under chunk i's processing+store.

#define CHUNK_TOKENS 32
#define CHUNK_BYTES  (CHUNK_TOKENS * 128 * 4)   // 16384
#define GRID_CTAS    444                        // ~3 per SM

__device__ __forceinline__ uint32_t smem_u32(const void* p) {
    uint64_t t;
    asm("cvta.to.shared.u64 %0, %1;" : "=l"(t) : "l"(p));
    return (uint32_t)t;
}

__device__ __forceinline__ void mbar_wait(uint32_t mbar, int phase) {
    uint32_t done;
    asm volatile(
        "{\n\t.reg .pred p;\n\t"
        "mbarrier.try_wait.parity.acquire.cta.shared::cta.b64 p, [%1], %2;\n\t"
        "selp.b32 %0, 1, 0, p;\n\t}"
        : "=r"(done) : "r"(mbar), "r"(phase) : "memory");
    if (!done) {
        asm volatile(
            "{\n\t.reg .pred P1;\n\t"
            "WL_%=:\n\t"
            "mbarrier.try_wait.parity.acquire.cta.shared::cta.b64 P1, [%0], %1, 0x989680;\n\t"
            "@P1 bra.uni WD_%=;\n\t"
            "bra.uni WL_%=;\n\t"
            "WD_%=:\n\t}"
            :: "r"(mbar), "r"(phase) : "memory");
    }
}

// Patch one active token located at stok (128 floats in smem).
__device__ __forceinline__ void process_active_smem(float* stok, const float4* s_coeff,
                                                    float b2v, int lane, unsigned FULL)
{
    // argmax over four 16-elem segments: [16,32)->lanes4..7, [32,48)->8..11,
    // [48,64)->12..15, [64,80)->16..19 (first-max wins: strict >, tie -> lower idx)
    float4 w = make_float4(0.f, 0.f, 0.f, 0.f);
    if (lane >= 4 && lane < 20)
        w = reinterpret_cast<const float4*>(stok)[lane];

    float best = w.x; int bidx = 0;
    if (w.y > best) { best = w.y; bidx = 1; }
    if (w.z > best) { best = w.z; bidx = 2; }
    if (w.w > best) { best = w.w; bidx = 3; }
    int gidx = ((lane & 3) << 2) | bidx;

    #pragma unroll
    for (int off = 1; off <= 2; off <<= 1) {
        float ob = __shfl_xor_sync(FULL, best, off);
        int   oi = __shfl_xor_sync(FULL, gidx, off);
        if (ob > best || (ob == best && oi < gidx)) { best = ob; gidx = oi; }
    }

    int a_lo = __shfl_sync(FULL, gidx, 4);
    int a_hi = __shfl_sync(FULL, gidx, 8);
    int b_lo = __shfl_sync(FULL, gidx, 12);
    int b_hi = __shfl_sync(FULL, gidx, 16);

    float fa = (float)(a_lo | (a_hi << 4));
    float fb = (float)(b_lo | (b_hi << 4));

    float acc = 0.0f;
    #pragma unroll
    for (int i = 0; i < 8; i++) {
        float4 c = s_coeff[lane + 32 * i];
        float h = fmaf(fa, c.x, fmaf(fb, c.y, c.z));
        h = fmaxf(h, 0.0f);
        acc = fmaf(h, c.w, acc);
    }
    #pragma unroll
    for (int off = 16; off; off >>= 1)
        acc += __shfl_xor_sync(FULL, acc, off);
    acc += b2v;

    int res = ((int)rintf(acc)) & 255;   // rintf == round-half-even == jnp.round
    if (lane == 0) {
        stok[80 + (res & 15)] += 2.0f;
        stok[96 + (res >> 4)] += 2.0f;
    }
}

__global__ void __launch_bounds__(256)
byte_mul_pipe_kernel(const float* __restrict__ x,
                     float* __restrict__ out,
                     const float* __restrict__ W1,
                     const float* __restrict__ b1,
                     const float* __restrict__ W2,
                     const float* __restrict__ b2,
                     int n_tokens)
{
    __shared__ __align__(128) float  s_buf[2][CHUNK_TOKENS * 128]; // 2 x 16 KB
    __shared__ __align__(16)  float4 s_coeff[256];                 // 4 KB
    __shared__ float s_b2;
    __shared__ __align__(8) uint64_t s_mbar[2];

    const unsigned FULL = 0xffffffffu;
    int tid  = threadIdx.x;
    int warp = tid >> 5;
    int lane = tid & 31;
    int bid  = blockIdx.x;
    int G    = gridDim.x;

    int total = n_tokens / CHUNK_TOKENS;   // full chunks

    uint32_t buf_addr[2], mbar_addr[2];
    buf_addr[0]  = smem_u32(s_buf[0]);
    buf_addr[1]  = smem_u32(s_buf[1]);
    mbar_addr[0] = smem_u32(&s_mbar[0]);
    mbar_addr[1] = smem_u32(&s_mbar[1]);

    if (tid == 0) {
        asm volatile("mbarrier.init.shared.b64 [%0], %1;" :: "r"(mbar_addr[0]), "r"(1) : "memory");
        asm volatile("mbarrier.init.shared.b64 [%0], %1;" :: "r"(mbar_addr[1]), "r"(1) : "memory");
    }
    __syncthreads();   // mbar init visible before any TMA

    // Prologue: issue load of first chunk, build coeff table under its latency.
    if (tid == 0 && bid < total) {
        const char* src = (const char*)(x + (size_t)bid * CHUNK_TOKENS * 128);
        asm volatile("mbarrier.arrive.expect_tx.shared.b64 _, [%0], %1;"
                     :: "r"(mbar_addr[0]), "r"((unsigned)CHUNK_BYTES) : "memory");
        asm volatile("cp.async.bulk.shared::cta.global.mbarrier::complete_tx::bytes "
                     "[%0], [%1], %2, [%3];"
                     :: "r"(buf_addr[0]), "l"(src), "r"((unsigned)CHUNK_BYTES), "r"(mbar_addr[0])
                     : "memory");
    }
    {
        int j = tid;
        s_coeff[j] = make_float4(W1[j], W1[256 + j],
                                 W1[29 * 256 + j] + b1[j], W2[j * 64 + 40]);
        if (j == 0) s_b2 = b2[40];
    }
    __syncthreads();
    float b2v = s_b2;

    int it = 0;
    for (int c = bid; c < total; c += G, ++it) {
        int s = it & 1;

        // Prefetch next chunk into the other slot (freed once its store's smem reads done).
        if (tid == 0) {
            int nxt = c + G;
            if (it > 0)
                asm volatile("cp.async.bulk.wait_group.read 0;" ::: "memory");
            if (nxt < total) {
                const char* src = (const char*)(x + (size_t)nxt * CHUNK_TOKENS * 128);
                asm volatile("mbarrier.arrive.expect_tx.shared.b64 _, [%0], %1;"
                             :: "r"(mbar_addr[s ^ 1]), "r"((unsigned)CHUNK_BYTES) : "memory");
                asm volatile("cp.async.bulk.shared::cta.global.mbarrier::complete_tx::bytes "
                             "[%0], [%1], %2, [%3];"
                             :: "r"(buf_addr[s ^ 1]), "l"(src), "r"((unsigned)CHUNK_BYTES),
                                "r"(mbar_addr[s ^ 1])
                             : "memory");
            }
        }

        // Wait current chunk, then patch active tokens in smem.
        mbar_wait(mbar_addr[s], (it >> 1) & 1);

        float* chunk = s_buf[s];
        {
            int tbase = warp * 4;     // 4 tokens per warp
            bool pred = false;
            if (lane < 4) {
                float2 m = *reinterpret_cast<const float2*>(&chunk[(tbase + lane) * 128]);
                pred = (m.x >= 0.5f) && (m.y >= 0.5f);
            }
            unsigned act = __ballot_sync(FULL, pred) & 0xFu;
            while (act) {
                int b = __ffs(act) - 1;
                act &= act - 1;
                process_active_smem(&chunk[(tbase + b) * 128], s_coeff, b2v, lane, FULL);
            }
        }
        __syncthreads();   // all patches done before bulk store reads smem

        if (tid == 0) {
            char* dst = (char*)(out + (size_t)c * CHUNK_TOKENS * 128);
            asm volatile("fence.proxy.async.shared::cta;" ::: "memory");
            asm volatile("cp.async.bulk.global.shared::cta.bulk_group [%0], [%1], %2;"
                         :: "l"(dst), "r"(buf_addr[s]), "r"((unsigned)CHUNK_BYTES) : "memory");
            asm volatile("cp.async.bulk.commit_group;" ::: "memory");
        }
    }

    // Ragged tail (never taken for 65536 tokens; kept for generality): block 0, warp 0.
    int rem0 = total * CHUNK_TOKENS;
    if (bid == 0 && warp == 0 && rem0 < n_tokens) {
        for (int t = rem0; t < n_tokens; t++) {
            const float4* xt = reinterpret_cast<const float4*>(x + (size_t)t * 128);
            float4*       ot = reinterpret_cast<float4*>(out + (size_t)t * 128);
            float4 v = xt[lane];
            int a = 0;
            if (lane == 0 && v.x >= 0.5f && v.y >= 0.5f) a = 1;
            a = __shfl_sync(FULL, a, 0);
            ot[lane] = v;
            if (a) {
                // reuse smem routine by staging through registers via global reads
                float bestv = 0.f; float4 w = make_float4(0.f,0.f,0.f,0.f);
                if (lane >= 4 && lane < 20) w = xt[lane];
                float best = w.x; int bidx = 0;
                if (w.y > best) { best = w.y; bidx = 1; }
                if (w.z > best) { best = w.z; bidx = 2; }
                if (w.w > best) { best = w.w; bidx = 3; }
                (void)bestv;
                int gidx = ((lane & 3) << 2) | bidx;
                #pragma unroll
                for (int off = 1; off <= 2; off <<= 1) {
                    float ob = __shfl_xor_sync(FULL, best, off);
                    int   oi = __shfl_xor_sync(FULL, gidx, off);
                    if (ob > best || (ob == best && oi < gidx)) { best = ob; gidx = oi; }
                }
                int a_lo = __shfl_sync(FULL, gidx, 4);
                int a_hi = __shfl_sync(FULL, gidx, 8);
                int b_lo = __shfl_sync(FULL, gidx, 12);
                int b_hi = __shfl_sync(FULL, gidx, 16);
                float fa = (float)(a_lo | (a_hi << 4));
                float fb = (float)(b_lo | (b_hi << 4));
                float acc = 0.0f;
                #pragma unroll
                for (int i = 0; i < 8; i++) {
                    float4 cc = s_coeff[lane + 32 * i];
                    float h = fmaf(fa, cc.x, fmaf(fb, cc.y, cc.z));
                    h = fmaxf(h, 0.0f);
                    acc = fmaf(h, cc.w, acc);
                }
                #pragma unroll
                for (int off = 16; off; off >>= 1)
                    acc += __shfl_xor_sync(FULL, acc, off);
                acc += b2v;
                int res = ((int)rintf(acc)) & 255;
                int e_lo = 80 + (res & 15);
                int e_hi = 96 + (res >> 4);
                if (lane == 0) {
                    out[(size_t)t * 128 + e_lo] = x[(size_t)t * 128 + e_lo] + 2.0f;
                    out[(size_t)t * 128 + e_hi] = x[(size_t)t * 128 + e_hi] + 2.0f;
                }
            }
        }
    }

    // Drain all bulk stores before exit.
    if (tid == 0)
        asm volatile("cp.async.bulk.wait_group 0;" ::: "memory");
}

extern "C" void kernel_launch(void* const* d_in, const int* in_sizes, int n_in,
                              void* d_out, int out_size)
{
    const float* x  = (const float*)d_in[0];  // [8, 8192, 128]
    const float* W1 = (const float*)d_in[1];  // [64, 256]
    const float* b1 = (const float*)d_in[2];  // [256]
    const float* W2 = (const float*)d_in[3];  // [256, 64]
    const float* b2 = (const float*)d_in[4];  // [64]
    float* out = (float*)d_out;

    int n_tokens = in_sizes[0] / 128;         // 65536

    byte_mul_pipe_kernel<<<GRID_CTAS, 256>>>(x, out, W1, b1, W2, b2, n_tokens);
}